// round 1
// baseline (speedup 1.0000x reference)
#include <cuda_runtime.h>

// Decode-mode paged attention, fp32, GQA 4.
// q: [B,H,D] | k_pages,v_pages: [KVH,P,T,D] | lengths: [B] | page_indices: [B,PPS]
// out: [B,H,D]

#define BB    32
#define HH    32
#define DD    128
#define KVHH  8
#define GG    4
#define NPAGE 2048
#define TT    64
#define PPSS  64
#define NSPLIT 4
#define PPER  (PPSS / NSPLIT)   // pages per split = 16
#define L2E   1.4426950408889634f

// Split-KV scratch (allocation-free rule: __device__ globals)
__device__ float g_m[NSPLIT * BB * HH];
__device__ float g_l[NSPLIT * BB * HH];
__device__ float g_o[NSPLIT * BB * HH * DD];

__global__ __launch_bounds__(128, 8)
void attn_partial(const float* __restrict__ q,
                  const float* __restrict__ kp,
                  const float* __restrict__ vp,
                  const int*   __restrict__ lengths,
                  const int*   __restrict__ pidx)
{
    const int split = blockIdx.x;
    const int kvh   = blockIdx.y;
    const int b     = blockIdx.z;
    const int warp  = threadIdx.x >> 5;     // = g (GQA head within group)
    const int lane  = threadIdx.x & 31;
    const int h     = kvh * GG + warp;
    const int slot  = (split * BB + b) * HH + h;

    const int len    = __ldg(&lengths[b]);
    const int npages = (len + TT - 1) / TT;
    const int p0     = split * PPER;
    const int p1     = min(p0 + PPER, npages);

    if (p0 >= p1) {
        if (lane == 0) { g_m[slot] = -1e30f; g_l[slot] = 0.0f; }
        float4 z = make_float4(0.f, 0.f, 0.f, 0.f);
        *(float4*)&g_o[(size_t)slot * DD + 4 * lane] = z;
        return;
    }

    // q slice for this head: lane l holds dims [4l, 4l+4)
    const float4 qv = *(const float4*)&q[((size_t)b * HH + h) * DD + 4 * lane];

    float  m = -1e30f, l = 0.0f;
    float4 o = make_float4(0.f, 0.f, 0.f, 0.f);

    for (int p = p0; p < p1; ++p) {
        const int page = __ldg(&pidx[b * PPSS + p]);
        const float* kb = kp + ((size_t)(kvh * NPAGE + page)) * TT * DD;
        const float* vb = vp + ((size_t)(kvh * NPAGE + page)) * TT * DD;
        const int nvalid = len - p * TT;   // >= 1 here; may exceed TT

        // ---- scores for 64 tokens; distribute one score per lane (2 regs) ----
        float s0 = -1e30f, s1 = -1e30f;
        #pragma unroll 8
        for (int t = 0; t < TT; ++t) {
            float4 kv = *(const float4*)&kb[t * DD + 4 * lane];
            float s = kv.x * qv.x + kv.y * qv.y + kv.z * qv.z + kv.w * qv.w;
            s += __shfl_xor_sync(0xffffffffu, s, 16);
            s += __shfl_xor_sync(0xffffffffu, s, 8);
            s += __shfl_xor_sync(0xffffffffu, s, 4);
            s += __shfl_xor_sync(0xffffffffu, s, 2);
            s += __shfl_xor_sync(0xffffffffu, s, 1);
            if (t >= nvalid) s = -1e30f;
            if ((t & 31) == lane) { if (t < 32) s0 = s; else s1 = s; }
        }

        // ---- page max, single rescale per page ----
        float pm = fmaxf(s0, s1);
        pm = fmaxf(pm, __shfl_xor_sync(0xffffffffu, pm, 16));
        pm = fmaxf(pm, __shfl_xor_sync(0xffffffffu, pm, 8));
        pm = fmaxf(pm, __shfl_xor_sync(0xffffffffu, pm, 4));
        pm = fmaxf(pm, __shfl_xor_sync(0xffffffffu, pm, 2));
        pm = fmaxf(pm, __shfl_xor_sync(0xffffffffu, pm, 1));

        const float newm = fmaxf(m, pm);
        const float r = exp2f((m - newm) * L2E);
        o.x *= r; o.y *= r; o.z *= r; o.w *= r;
        l *= r;
        m = newm;

        // 64 distinct exps in 2 warp-wide MUFU
        const float e0 = exp2f((s0 - m) * L2E);   // 0 for invalid tokens
        const float e1 = exp2f((s1 - m) * L2E);

        float ls = e0 + e1;
        ls += __shfl_xor_sync(0xffffffffu, ls, 16);
        ls += __shfl_xor_sync(0xffffffffu, ls, 8);
        ls += __shfl_xor_sync(0xffffffffu, ls, 4);
        ls += __shfl_xor_sync(0xffffffffu, ls, 2);
        ls += __shfl_xor_sync(0xffffffffu, ls, 1);
        l += ls;

        // ---- o += p_t * v_t ----
        #pragma unroll 8
        for (int t = 0; t < TT; ++t) {
            const float pt = __shfl_sync(0xffffffffu, (t < 32) ? e0 : e1, t & 31);
            float4 vv = *(const float4*)&vb[t * DD + 4 * lane];
            o.x += pt * vv.x;
            o.y += pt * vv.y;
            o.z += pt * vv.z;
            o.w += pt * vv.w;
        }
    }

    if (lane == 0) { g_m[slot] = m; g_l[slot] = l; }
    *(float4*)&g_o[(size_t)slot * DD + 4 * lane] = o;
}

__global__ __launch_bounds__(128)
void attn_reduce(float* __restrict__ out)
{
    const int idx  = blockIdx.x * 4 + (threadIdx.x >> 5);  // (b*H + h)
    const int lane = threadIdx.x & 31;

    float M = -1e30f;
    #pragma unroll
    for (int j = 0; j < NSPLIT; ++j)
        M = fmaxf(M, g_m[j * BB * HH + idx]);

    float L = 0.0f;
    float4 acc = make_float4(0.f, 0.f, 0.f, 0.f);
    #pragma unroll
    for (int j = 0; j < NSPLIT; ++j) {
        const int sl = j * BB * HH + idx;
        const float f = exp2f((g_m[sl] - M) * L2E);
        L += f * g_l[sl];
        float4 ov = *(const float4*)&g_o[(size_t)sl * DD + 4 * lane];
        acc.x += f * ov.x;
        acc.y += f * ov.y;
        acc.z += f * ov.z;
        acc.w += f * ov.w;
    }

    const float inv = 1.0f / L;  // split 0 always non-empty -> L > 0
    float4 res = make_float4(acc.x * inv, acc.y * inv, acc.z * inv, acc.w * inv);
    *(float4*)&out[(size_t)idx * DD + 4 * lane] = res;
}

extern "C" void kernel_launch(void* const* d_in, const int* in_sizes, int n_in,
                              void* d_out, int out_size)
{
    const float* q   = (const float*)d_in[0];
    const float* kp  = (const float*)d_in[1];
    const float* vp  = (const float*)d_in[2];
    const int*   len = (const int*)d_in[3];
    const int*   pid = (const int*)d_in[4];
    float* out = (float*)d_out;

    dim3 grid(NSPLIT, KVHH, BB);
    attn_partial<<<grid, 128>>>(q, kp, vp, len, pid);
    attn_reduce<<<(BB * HH) / 4, 128>>>(out);
}

// round 6
// speedup vs baseline: 1.8811x; 1.8811x over previous
#include <cuda_runtime.h>
#include <cstdint>

// Decode-mode paged attention, fp32, GQA 4. Split-KV flash decode.
// q: [B,H,D] | k_pages,v_pages: [KVH,P,T,D] | lengths: [B] | page_indices: [B,PPS]

#define BB     32
#define HH     32
#define DD     128
#define KVHH   8
#define GG     4
#define NPAGE  2048
#define TT     64
#define PPSS   64
#define NSPLIT 16
#define PPER   (PPSS / NSPLIT)     // 4 pages per split
#define TOKSPL (PPER * TT)         // 256 tokens per split
#define TILE   32                  // tokens per smem tile (half page)
#define L2E    1.4426950408889634f

// Split-KV scratch (__device__ globals per allocation rules)
__device__ float g_m[NSPLIT * BB * HH];
__device__ float g_l[NSPLIT * BB * HH];
__device__ float g_o[NSPLIT * BB * HH * DD];

__device__ __forceinline__ void cp16(uint32_t dst, const void* src) {
    asm volatile("cp.async.cg.shared.global [%0], [%1], 16;\n" :: "r"(dst), "l"(src));
}

__global__ __launch_bounds__(128, 6)
void attn_partial(const float* __restrict__ q,
                  const float* __restrict__ kp,
                  const float* __restrict__ vp,
                  const int*   __restrict__ lengths,
                  const int*   __restrict__ pidx)
{
    // K tile double buffer: [2][token 0..31][chunk 0..31] float4, XOR-swizzled
    __shared__ float4 ksm[2][TILE * 32];
    __shared__ float4 qs[GG][32];

    const int split = blockIdx.x;
    const int kvh   = blockIdx.y;
    const int b     = blockIdx.z;
    const int tid   = threadIdx.x;
    const int warp  = tid >> 5;      // GQA head within group
    const int lane  = tid & 31;
    const int h     = kvh * GG + warp;
    const int slot  = (split * BB + b) * HH + h;

    const int len  = __ldg(&lengths[b]);
    const int tok0 = split * TOKSPL;
    const int ntok = min(len - tok0, TOKSPL);

    if (ntok <= 0) {
        if (lane == 0) { g_m[slot] = -1e30f; g_l[slot] = 0.0f; }
        float4 z = make_float4(0.f, 0.f, 0.f, 0.f);
        *(float4*)&g_o[(size_t)slot * DD + 4 * lane] = z;
        return;
    }
    const int ntiles = (ntok + TILE - 1) / TILE;

    // q slice for this head: chunk c holds dims [4c,4c+4)
    qs[warp][lane] = *(const float4*)&q[((size_t)b * HH + h) * DD + 4 * lane];
    __syncwarp();

    const uint32_t smem_base = (uint32_t)__cvta_generic_to_shared(&ksm[0][0]);
    const int pbase = b * PPSS + split * PPER;

    // ---- async copy of K tile i into buffer buf (swizzled) ----
    auto issue_copy = [&](int buf, int i) {
        const int page = __ldg(&pidx[pbase + (i >> 1)]);
        const float* base = kp + ((size_t)(kvh * NPAGE + page)) * TT * DD
                               + (size_t)(i & 1) * TILE * DD;
        #pragma unroll
        for (int j = 0; j < 8; ++j) {
            int idx = j * 128 + tid;
            int t = idx >> 5, c = idx & 31;
            uint32_t dst = smem_base
                         + (uint32_t)(buf * (TILE * 32) + t * 32 + (c ^ t)) * 16u;
            cp16(dst, base + t * DD + c * 4);
        }
        asm volatile("cp.async.commit_group;\n");
    };

    float  m = -1e30f, l = 0.0f;
    float4 o = make_float4(0.f, 0.f, 0.f, 0.f);

    issue_copy(0, 0);

    for (int i = 0; i < ntiles; ++i) {
        if (i + 1 < ntiles) {
            issue_copy((i + 1) & 1, i + 1);
            asm volatile("cp.async.wait_group 1;\n");
        } else {
            asm volatile("cp.async.wait_group 0;\n");
        }
        __syncthreads();

        // ---- score: lane owns token = lane of this tile ----
        const float4* kb = &ksm[i & 1][0];
        float4 acc = make_float4(0.f, 0.f, 0.f, 0.f);
        #pragma unroll
        for (int c = 0; c < 32; ++c) {
            float4 q4 = qs[warp][c];                 // LDS broadcast
            float4 k4 = kb[lane * 32 + (c ^ lane)];  // conflict-free
            acc.x += q4.x * k4.x;
            acc.y += q4.y * k4.y;
            acc.z += q4.z * k4.z;
            acc.w += q4.w * k4.w;
        }
        float s = (acc.x + acc.y) + (acc.z + acc.w);
        if (tok0 + i * TILE + lane >= len) s = -1e30f;

        // ---- tile softmax (once per 32 tokens) ----
        float pm = s;
        pm = fmaxf(pm, __shfl_xor_sync(0xffffffffu, pm, 16));
        pm = fmaxf(pm, __shfl_xor_sync(0xffffffffu, pm, 8));
        pm = fmaxf(pm, __shfl_xor_sync(0xffffffffu, pm, 4));
        pm = fmaxf(pm, __shfl_xor_sync(0xffffffffu, pm, 2));
        pm = fmaxf(pm, __shfl_xor_sync(0xffffffffu, pm, 1));

        const float newm = fmaxf(m, pm);
        const float r = exp2f((m - newm) * L2E);
        o.x *= r; o.y *= r; o.z *= r; o.w *= r;
        l *= r;
        m = newm;

        const float e = exp2f((s - m) * L2E);   // 0 for masked tokens
        float ls = e;
        ls += __shfl_xor_sync(0xffffffffu, ls, 16);
        ls += __shfl_xor_sync(0xffffffffu, ls, 8);
        ls += __shfl_xor_sync(0xffffffffu, ls, 4);
        ls += __shfl_xor_sync(0xffffffffu, ls, 2);
        ls += __shfl_xor_sync(0xffffffffu, ls, 1);
        l += ls;

        // ---- o += p_t * v_t  (coalesced global V, L1-shared across warps) ----
        const int page = __ldg(&pidx[pbase + (i >> 1)]);
        const float* vb = vp + ((size_t)(kvh * NPAGE + page)) * TT * DD
                             + (size_t)(i & 1) * TILE * DD + 4 * lane;
        #pragma unroll
        for (int t = 0; t < TILE; ++t) {
            const float pt = __shfl_sync(0xffffffffu, e, t);
            float4 v4 = *(const float4*)(vb + t * DD);
            o.x += pt * v4.x;
            o.y += pt * v4.y;
            o.z += pt * v4.z;
            o.w += pt * v4.w;
        }
        __syncthreads();   // buffer reuse guard
    }

    if (lane == 0) { g_m[slot] = m; g_l[slot] = l; }
    *(float4*)&g_o[(size_t)slot * DD + 4 * lane] = o;
}

__global__ __launch_bounds__(128)
void attn_reduce(float* __restrict__ out)
{
    const int idx  = blockIdx.x * 4 + (threadIdx.x >> 5);  // (b*H + h)
    const int lane = threadIdx.x & 31;

    float M = -1e30f;
    #pragma unroll
    for (int j = 0; j < NSPLIT; ++j)
        M = fmaxf(M, g_m[j * BB * HH + idx]);

    float L = 0.0f;
    float4 acc = make_float4(0.f, 0.f, 0.f, 0.f);
    #pragma unroll
    for (int j = 0; j < NSPLIT; ++j) {
        const int sl = j * BB * HH + idx;
        const float f = exp2f((g_m[sl] - M) * L2E);
        L += f * g_l[sl];
        float4 ov = *(const float4*)&g_o[(size_t)sl * DD + 4 * lane];
        acc.x += f * ov.x;
        acc.y += f * ov.y;
        acc.z += f * ov.z;
        acc.w += f * ov.w;
    }

    const float inv = 1.0f / L;  // split 0 always non-empty -> L > 0
    float4 res = make_float4(acc.x * inv, acc.y * inv, acc.z * inv, acc.w * inv);
    *(float4*)&out[(size_t)idx * DD + 4 * lane] = res;
}

extern "C" void kernel_launch(void* const* d_in, const int* in_sizes, int n_in,
                              void* d_out, int out_size)
{
    const float* q   = (const float*)d_in[0];
    const float* kp  = (const float*)d_in[1];
    const float* vp  = (const float*)d_in[2];
    const int*   len = (const int*)d_in[3];
    const int*   pid = (const int*)d_in[4];
    float* out = (float*)d_out;

    dim3 grid(NSPLIT, KVHH, BB);
    attn_partial<<<grid, 128>>>(q, kp, vp, len, pid);
    attn_reduce<<<(BB * HH) / 4, 128>>>(out);
}